// round 8
// baseline (speedup 1.0000x reference)
#include <cuda_runtime.h>
#include <math.h>

#define H_IN   192
#define W_IN   192
#define HOUT   96
#define WOUT   96
#define C1     32
#define NN     17
#define BATCH  128

// Block: 32x16 output px = 16x8 Winograd tiles (2x2 px each)
#define BX     32
#define BY     16
#define NTX    16          // tiles in x
#define NTY    8           // tiles in y
#define NTILE  (NTX*NTY)   // 128

// h tile: gy in [y0-1, y0+16], gx in [x0-1, x0+32] -> 18 x 34, stride 36
#define HROWS  18
#define HCOLS  34
#define HSTR2  36
#define SMH    (HROWS*HSTR2)      // 648 floats per channel

// input tile: iy in [2y0-2, 2y0+34] (37), ix in [2x0-2, 2x0+66] (69), stride 72
#define ITSY   37
#define ITSX   69
#define ISTR   72
#define NPOS   (HROWS*HCOLS)      // 612 conv1 positions

#define SM_W1T (C1*12)            // 384 floats
#define SM_IN  (ITSY*ISTR)        // 2664 floats
#define SM_H   (C1*SMH)           // 20736 floats
#define SM_U   (C1*NN*16)         // 8704 floats
#define SM_FLOATS (SM_W1T + SM_IN + SM_H + SM_U)
#define SM_BYTES  (SM_FLOATS * 4)   // ~130 KB

__constant__ float cB1[C1];
__constant__ float cB2[NN];

__device__ float g_cms[(size_t)BATCH*NN*HOUT*WOUT];

// ---------- output chunk emitter (static NB/CH so MA/MB indexing stays in regs) ----------
template<int NB, int CH>
static __device__ __forceinline__ void emit_chunk(
    const float (&MA)[NN][4], const float (&MB)[NN][4],
    float* M_s, int tA, int tB, int g, int tid,
    int b, int x0, int y0)
{
    #pragma unroll
    for (int nl = 0; nl < CH; nl++) {
        const int n = NB + nl;
        *(float4*)(M_s + (tA*6 + nl)*16 + 4*g) =
            make_float4(MA[n][0], MA[n][1], MA[n][2], MA[n][3]);
        *(float4*)(M_s + (tB*6 + nl)*16 + 4*g) =
            make_float4(MB[n][0], MB[n][1], MB[n][2], MB[n][3]);
    }
    __syncthreads();

    for (int i = tid; i < NTILE*CH; i += 256) {
        const int t  = i & (NTILE-1);
        const int nl = i >> 7;
        const int n  = NB + nl;
        const float* mp = M_s + (t*6 + nl)*16;
        const float4 m0 = *(const float4*)(mp);       // V-row 0 (k0..3)
        const float4 m1 = *(const float4*)(mp + 4);
        const float4 m2 = *(const float4*)(mp + 8);
        const float4 m3 = *(const float4*)(mp + 12);

        // Z = A^T M ; Y = Z A
        const float z00 = m0.x + m1.x + m2.x;
        const float z01 = m0.y + m1.y + m2.y;
        const float z02 = m0.z + m1.z + m2.z;
        const float z03 = m0.w + m1.w + m2.w;
        const float z10 = m1.x - m2.x - m3.x;
        const float z11 = m1.y - m2.y - m3.y;
        const float z12 = m1.z - m2.z - m3.z;
        const float z13 = m1.w - m2.w - m3.w;
        const float bb = cB2[n];
        const float y00 = z00 + z01 + z02 + bb;
        const float y01 = z01 - z02 - z03 + bb;
        const float y10 = z10 + z11 + z12 + bb;
        const float y11 = z11 - z12 - z13 + bb;

        const int ty_t = t >> 4, tx_t = t & 15;
        const int gy = y0 + 2*ty_t, gx = x0 + 2*tx_t;
        float* o = g_cms + ((size_t)(b*NN + n)*HOUT + gy)*WOUT + gx;
        *(float2*)o          = make_float2(y00, y01);
        *(float2*)(o + WOUT) = make_float2(y10, y11);
    }
    __syncthreads();
}

__global__ __launch_bounds__(256, 1)
void conv_winograd_kernel(const float* __restrict__ crops,
                          const float* __restrict__ W1g,
                          const float* __restrict__ W2g)
{
    extern __shared__ float sm[];
    float* s_w1t = sm;                 // [C1][12]
    float* s_in  = sm + SM_W1T;        // [ITSY][ISTR]
    float* s_h   = s_in + SM_IN;       // [C1][HROWS][HSTR2]
    float* s_U   = s_h + SM_H;         // [C1*NN][16]

    const int tid = threadIdx.x;
    const int x0  = blockIdx.x * BX;
    const int y0  = blockIdx.y * BY;
    const int b   = blockIdx.z;

    // ---- stage transposed W1 (288 entries, strided) ----
    for (int i = tid; i < 9*C1; i += 256) {
        int k = i / C1, c = i - k*C1;
        s_w1t[c*12 + k] = W1g[i];
    }
    // ---- stage input tile ----
    const float* img = crops + (size_t)b * H_IN * W_IN;
    for (int i = tid; i < ITSY*ITSX; i += 256) {
        int r  = i / ITSX, cc = i - r*ITSX;
        int iy = 2*y0 - 2 + r;
        int ix = 2*x0 - 2 + cc;
        float v = 0.f;
        if (iy >= 0 && iy < H_IN && ix >= 0 && ix < W_IN) v = img[iy*W_IN + ix];
        s_in[r*ISTR + cc] = v;
    }
    // ---- precompute U = G g G^T per (c,n), rows as float4 ----
    for (int i = tid; i < C1*NN; i += 256) {
        const int c = i / NN, n = i - c*NN;
        float gr[3][3];
        #pragma unroll
        for (int r = 0; r < 3; r++)
            #pragma unroll
            for (int s = 0; s < 3; s++)
                gr[r][s] = W2g[((r*3 + s)*C1 + c)*NN + n];
        float T[4][3];
        #pragma unroll
        for (int s = 0; s < 3; s++) {
            const float t02 = gr[0][s] + gr[2][s];
            T[0][s] = gr[0][s];
            T[1][s] = 0.5f*(t02 + gr[1][s]);
            T[2][s] = 0.5f*(t02 - gr[1][s]);
            T[3][s] = gr[2][s];
        }
        float* up = s_U + i*16;
        #pragma unroll
        for (int r = 0; r < 4; r++) {
            const float u02 = T[r][0] + T[r][2];
            *(float4*)(up + 4*r) = make_float4(
                T[r][0], 0.5f*(u02 + T[r][1]), 0.5f*(u02 - T[r][1]), T[r][2]);
        }
    }
    __syncthreads();

    // ---- conv1: all 32 channels -> s_h (zero outside [0,96) for SAME pad) ----
    float in9[3][9];
    int   offh[3];
    bool  pmask[3], pborder[3];
    #pragma unroll
    for (int i = 0; i < 3; i++) {
        const int p = tid + i*256;
        pmask[i] = (p < NPOS);
        const int pp = pmask[i] ? p : 0;
        const int ly = pp / HCOLS - 1;
        const int lx = pp - (pp / HCOLS)*HCOLS - 1;
        offh[i] = (ly+1)*HSTR2 + (lx+1);
        const int gy = y0 + ly, gx = x0 + lx;
        pborder[i] = (gy >= 0) & (gy < HOUT) & (gx >= 0) & (gx < WOUT);
        const float* r0 = s_in + (2*ly + 2)*ISTR + (2*lx + 2);
        #pragma unroll
        for (int ky = 0; ky < 3; ky++) {
            const float2 v2 = *(const float2*)(r0 + ky*ISTR);   // even offset
            in9[i][ky*3+0] = v2.x;
            in9[i][ky*3+1] = v2.y;
            in9[i][ky*3+2] = r0[ky*ISTR + 2];
        }
    }
    #pragma unroll 1
    for (int c = 0; c < C1; c++) {
        const float4 wa = *(const float4*)(s_w1t + c*12);
        const float4 wb = *(const float4*)(s_w1t + c*12 + 4);
        const float  w8 = s_w1t[c*12 + 8];
        const float  b1c = cB1[c];
        float* hc = s_h + c*SMH;
        #pragma unroll
        for (int i = 0; i < 3; i++) {
            if (!pmask[i]) continue;
            float a = b1c;
            a = fmaf(in9[i][0], wa.x, a);
            a = fmaf(in9[i][1], wa.y, a);
            a = fmaf(in9[i][2], wa.z, a);
            a = fmaf(in9[i][3], wa.w, a);
            a = fmaf(in9[i][4], wb.x, a);
            a = fmaf(in9[i][5], wb.y, a);
            a = fmaf(in9[i][6], wb.z, a);
            a = fmaf(in9[i][7], wb.w, a);
            a = fmaf(in9[i][8], w8,   a);
            a = fmaxf(a, 0.f);
            hc[offh[i]] = pborder[i] ? a : 0.f;
        }
    }
    __syncthreads();

    // ---- conv2 Winograd: thread = (tile pair, V-row g) ----
    const int g   = tid & 3;
    const int pxp = (tid >> 2) & 7;
    const int py  = tid >> 5;

    // B^T row combos: W[j] = d[rA][j] + sgn*d[rB][j]
    int rA, rB; float sgn;
    if      (g == 0) { rA = 0; rB = 2; sgn = -1.f; }
    else if (g == 1) { rA = 1; rB = 2; sgn =  1.f; }
    else if (g == 2) { rA = 2; rB = 1; sgn = -1.f; }
    else             { rA = 1; rB = 3; sgn = -1.f; }
    const int rowA = (2*py + rA)*HSTR2;
    const int rowB = (2*py + rB)*HSTR2;
    const int colb = 4*pxp;      // s_h col base (aligned: multiple of 4 floats)

    float MA[NN][4], MB[NN][4];
    #pragma unroll
    for (int n = 0; n < NN; n++) {
        MA[n][0]=0.f; MA[n][1]=0.f; MA[n][2]=0.f; MA[n][3]=0.f;
        MB[n][0]=0.f; MB[n][1]=0.f; MB[n][2]=0.f; MB[n][3]=0.f;
    }

    #pragma unroll 1
    for (int c = 0; c < C1; c++) {
        const float* hc = s_h + c*SMH;
        const float* pa = hc + rowA + colb;
        const float* pb = hc + rowB + colb;
        const float4 a4 = *(const float4*)pa;
        const float2 a2 = *(const float2*)(pa + 4);
        const float4 b4 = *(const float4*)pb;
        const float2 b2 = *(const float2*)(pb + 4);

        const float W0 = fmaf(sgn, b4.x, a4.x);
        const float W1 = fmaf(sgn, b4.y, a4.y);
        const float W2 = fmaf(sgn, b4.z, a4.z);
        const float W3 = fmaf(sgn, b4.w, a4.w);
        const float W4 = fmaf(sgn, b2.x, a2.x);
        const float W5 = fmaf(sgn, b2.y, a2.y);

        const float VA0 = W0 - W2, VA1 = W1 + W2, VA2 = W2 - W1, VA3 = W1 - W3;
        const float VB0 = W2 - W4, VB1 = W3 + W4, VB2 = W4 - W3, VB3 = W3 - W5;

        const float4* up = (const float4*)(s_U + c*NN*16) + g;
        #pragma unroll
        for (int n = 0; n < NN; n++) {
            const float4 u = up[n*4];
            MA[n][0] = fmaf(u.x, VA0, MA[n][0]);
            MA[n][1] = fmaf(u.y, VA1, MA[n][1]);
            MA[n][2] = fmaf(u.z, VA2, MA[n][2]);
            MA[n][3] = fmaf(u.w, VA3, MA[n][3]);
            MB[n][0] = fmaf(u.x, VB0, MB[n][0]);
            MB[n][1] = fmaf(u.y, VB1, MB[n][1]);
            MB[n][2] = fmaf(u.z, VB2, MB[n][2]);
            MB[n][3] = fmaf(u.w, VB3, MB[n][3]);
        }
    }
    __syncthreads();   // s_h dead; M_s reuses it

    // ---- output transform in 3 static n-chunks ----
    float* M_s = s_h;                       // 128*6*16 = 12288 floats fits
    const int tA = py*NTX + 2*pxp;
    const int tB = tA + 1;
    emit_chunk<0, 6>(MA, MB, M_s, tA, tB, g, tid, b, x0, y0);
    emit_chunk<6, 6>(MA, MB, M_s, tA, tB, g, tid, b, x0, y0);
    emit_chunk<12,5>(MA, MB, M_s, tA, tB, g, tid, b, x0, y0);
}

// one block per (b, n): argmax (first-index ties) + quarter-pixel refine + threshold + x2
__global__ void peaks_kernel(float* __restrict__ out)
{
    const int bn = blockIdx.x;
    const float* cm = g_cms + (size_t)bn * HOUT * WOUT;
    const int tid = threadIdx.x;

    float best = -INFINITY;
    int bidx = 0;
    for (int i = tid; i < HOUT*WOUT; i += 256) {
        float v = cm[i];
        if (v > best) { best = v; bidx = i; }
    }

    __shared__ float sv[256];
    __shared__ int   si[256];
    sv[tid] = best; si[tid] = bidx;
    __syncthreads();
    for (int s = 128; s > 0; s >>= 1) {
        if (tid < s) {
            float ov = sv[tid + s]; int oi = si[tid + s];
            if (ov > sv[tid] || (ov == sv[tid] && oi < si[tid])) {
                sv[tid] = ov; si[tid] = oi;
            }
        }
        __syncthreads();
    }

    if (tid == 0) {
        float val = sv[0];
        int idx = si[0];
        int yi = idx / WOUT;
        int xi = idx - yi * WOUT;

        int xm = max(xi-1, 0), xp = min(xi+1, WOUT-1);
        int ym = max(yi-1, 0), yp = min(yi+1, HOUT-1);
        float ddx = cm[yi*WOUT + xp] - cm[yi*WOUT + xm];
        float ddy = cm[yp*WOUT + xi] - cm[ym*WOUT + xi];
        float sx = (ddx > 0.f) ? 1.f : ((ddx < 0.f) ? -1.f : 0.f);
        float sy = (ddy > 0.f) ? 1.f : ((ddy < 0.f) ? -1.f : 0.f);

        float px = ((float)xi + 0.25f*sx) * 2.0f;
        float py = ((float)yi + 0.25f*sy) * 2.0f;
        if (!(val >= 0.2f)) { px = nanf(""); py = nanf(""); }

        out[bn*3 + 0] = px;
        out[bn*3 + 1] = py;
        out[bn*3 + 2] = val;
    }
}

extern "C" void kernel_launch(void* const* d_in, const int* in_sizes, int n_in,
                              void* d_out, int out_size)
{
    const float* crops = (const float*)d_in[0];
    const float* W1    = (const float*)d_in[1];
    const float* b1    = (const float*)d_in[2];
    const float* W2    = (const float*)d_in[3];
    const float* b2    = (const float*)d_in[4];
    float* out = (float*)d_out;

    cudaMemcpyToSymbolAsync(cB1, b1, C1*sizeof(float), 0, cudaMemcpyDeviceToDevice, 0);
    cudaMemcpyToSymbolAsync(cB2, b2, NN*sizeof(float), 0, cudaMemcpyDeviceToDevice, 0);

    cudaFuncSetAttribute(conv_winograd_kernel,
                         cudaFuncAttributeMaxDynamicSharedMemorySize, SM_BYTES);

    dim3 grid(WOUT/BX, HOUT/BY, BATCH);   // 3 x 6 x 128
    conv_winograd_kernel<<<grid, 256, SM_BYTES>>>(crops, W1, W2);

    peaks_kernel<<<BATCH*NN, 256>>>(out);
}